// round 16
// baseline (speedup 1.0000x reference)
#include <cuda_runtime.h>
#include <cuda_fp16.h>
#include <cstdint>

// ---------------------------------------------------------------------------
// GCN: 3 layers of  h = relu(segment_sum_{(s->d)}(h_prev[s]) @ W + b)
// Aggregate-before-transform (segment_sum is linear).
// Round 16: 4-edge fp16 tree accumulation in aggregation (pairs -> quads via
//           HADD2 before fp32 convert; ~30% fewer issue-bound ops on top of
//           R15's pair-sums; measured error headroom covers the extra level).
// ---------------------------------------------------------------------------

#define N_NODES 50000
#define N_EDGES 800000
#define FMAX    256
#define NOUT    256

// Scratch (static device globals — zero-initialized; no runtime allocation).
__device__ __half  g_h[(size_t)N_NODES * FMAX];     // activations (fp16)
__device__ __half  g_a[(size_t)N_NODES * FMAX];     // aggregates  (fp16)
__device__ __half  g_x16[(size_t)N_NODES * 128];    // x quantized to fp16
__device__ __half  g_wt[3][256 * 256];              // W^T fp16  [N][K]
__device__ int     g_counts[N_NODES];
__device__ int     g_offsets[N_NODES + 1];
__device__ int     g_cursor[N_NODES];
__device__ int     g_perm_src[N_EDGES];

// ---------------------------------------------------------------------------
// Per-block edge-index dtype detection (JAX may have downcast int64->int32).
// ---------------------------------------------------------------------------
__device__ __forceinline__ int block_detect_is64(const void* ei)
{
    long long v = ((const long long*)ei)[threadIdx.x & 255];
    int ok = (v >= 0 && v < N_NODES);
    return __syncthreads_and(ok);
}

// ---------------------------------------------------------------------------
// hist_kernel: in-degree histogram + x fp32->fp16 conversion (folded in).
// ---------------------------------------------------------------------------
__global__ __launch_bounds__(256) void hist_kernel(const void* __restrict__ ei,
                                                   const float* __restrict__ x)
{
    int is64 = block_detect_is64(ei);
    int e = blockIdx.x * blockDim.x + threadIdx.x;
    if (e >= N_EDGES) return;

    // x conversion: elements e and e + N_EDGES of the float4 view.
    {
        const float4* xf = reinterpret_cast<const float4*>(x);
        uint2* xo = reinterpret_cast<uint2*>(g_x16);
        float4 v0 = xf[e];
        float4 v1 = xf[e + N_EDGES];
        __half2 a0 = __floats2half2_rn(v0.x, v0.y);
        __half2 a1 = __floats2half2_rn(v0.z, v0.w);
        __half2 b0 = __floats2half2_rn(v1.x, v1.y);
        __half2 b1 = __floats2half2_rn(v1.z, v1.w);
        xo[e] = make_uint2(*reinterpret_cast<unsigned*>(&a0),
                           *reinterpret_cast<unsigned*>(&a1));
        xo[e + N_EDGES] = make_uint2(*reinterpret_cast<unsigned*>(&b0),
                                     *reinterpret_cast<unsigned*>(&b1));
    }

    long long d = is64 ? ((const long long*)ei)[N_EDGES + e]
                       : (long long)((const int*)ei)[N_EDGES + e];
    if ((unsigned long long)d < N_NODES) atomicAdd(&g_counts[(int)d], 1);
}

__global__ __launch_bounds__(1024) void scan_kernel()
{
    __shared__ int partial[1024];
    int t = threadIdx.x;
    const int CHUNK = (N_NODES + 1023) / 1024;
    int beg = t * CHUNK;
    int end = beg + CHUNK; if (end > N_NODES) end = N_NODES;
    if (beg > N_NODES) beg = N_NODES;

    int s = 0;
    for (int i = beg; i < end; i++) s += g_counts[i];
    partial[t] = s;
    __syncthreads();
    for (int off = 1; off < 1024; off <<= 1) {
        int v = (t >= off) ? partial[t - off] : 0;
        __syncthreads();
        partial[t] += v;
        __syncthreads();
    }
    int prefix = (t == 0) ? 0 : partial[t - 1];
    for (int i = beg; i < end; i++) {
        g_offsets[i] = prefix;
        g_cursor[i]  = prefix;
        prefix += g_counts[i];
        g_counts[i] = 0;                   // re-zero for next graph replay
    }
    if (t == 1023) g_offsets[N_NODES] = partial[1023];
}

__global__ __launch_bounds__(256) void fill_kernel(const void* __restrict__ ei)
{
    int is64 = block_detect_is64(ei);
    int e = blockIdx.x * blockDim.x + threadIdx.x;
    if (e >= N_EDGES) return;
    long long d, s;
    if (is64) {
        d = ((const long long*)ei)[N_EDGES + e];
        s = ((const long long*)ei)[e];
    } else {
        d = ((const int*)ei)[N_EDGES + e];
        s = ((const int*)ei)[e];
    }
    if ((unsigned long long)d >= N_NODES || (unsigned long long)s >= N_NODES)
        return;
    int pos = atomicAdd(&g_cursor[(int)d], 1);
    g_perm_src[pos] = (int)s;
}

// ---------------------------------------------------------------------------
// Weight prep: W^T quantized to fp16.  wt[n*K + k] = (half)W[k*N + n].
// ---------------------------------------------------------------------------
__global__ void wsplit_kernel(const float* __restrict__ W1,
                              const float* __restrict__ W2,
                              const float* __restrict__ W3)
{
    int n = blockIdx.x;
    int l = blockIdx.y;
    const float* W = (l == 0) ? W1 : (l == 1) ? W2 : W3;
    int K = (l == 0) ? 128 : 256;
    __half* wt = g_wt[l];
    for (int k = threadIdx.x; k < K; k += blockDim.x)
        wt[n * K + k] = __float2half_rn(W[(size_t)k * NOUT + n]);
}

// ---------------------------------------------------------------------------
// CSR aggregation, fp16 input -> fp16 aggregate.
// 4-edge fp16 tree (pairs -> quads via HADD2, ~2^-12 noise per level) before
// fp32 accumulation: per 8 edges, 80 -> 56 issue-bound ops vs pair-only.
// CH = F/8 threads per node, uint4 (8-half) gathers, 8-edge unroll.
// ---------------------------------------------------------------------------
template <int F>
__global__ __launch_bounds__(256) void aggregate_f16in(
    const __half* __restrict__ h,
    __half* __restrict__ a_out)
{
    constexpr int CH  = F / 8;            // 16 (F=128) / 32 (F=256)
    constexpr int NPB = 256 / CH;
    int node = blockIdx.x * NPB + threadIdx.x / CH;
    int c    = threadIdx.x % CH;
    if (node >= N_NODES) return;

    int beg = g_offsets[node];
    int end = g_offsets[node + 1];

    float acc[8] = {0.f, 0.f, 0.f, 0.f, 0.f, 0.f, 0.f, 0.f};
    int i = beg;
    for (; i + 8 <= end; i += 8) {
        int s[8];
        #pragma unroll
        for (int j = 0; j < 8; j++) s[j] = g_perm_src[i + j];
        uint4 v[8];
        #pragma unroll
        for (int j = 0; j < 8; j++)
            v[j] = *reinterpret_cast<const uint4*>(h + (size_t)s[j] * F + c * 8);
        // fp16 tree: pairs (16 HADD2) -> quads (8 HADD2) -> convert+accum.
        #pragma unroll
        for (int qd = 0; qd < 2; qd++) {
            const __half2* p0 = reinterpret_cast<const __half2*>(&v[4 * qd + 0]);
            const __half2* p1 = reinterpret_cast<const __half2*>(&v[4 * qd + 1]);
            const __half2* p2 = reinterpret_cast<const __half2*>(&v[4 * qd + 2]);
            const __half2* p3 = reinterpret_cast<const __half2*>(&v[4 * qd + 3]);
            #pragma unroll
            for (int q = 0; q < 4; q++) {
                __half2 qs = __hadd2(__hadd2(p0[q], p1[q]),
                                     __hadd2(p2[q], p3[q]));
                float2 f = __half22float2(qs);
                acc[2 * q] += f.x; acc[2 * q + 1] += f.y;
            }
        }
    }
    for (; i < end; i++) {
        int s = g_perm_src[i];
        uint4 v = *reinterpret_cast<const uint4*>(h + (size_t)s * F + c * 8);
        const __half2* p = reinterpret_cast<const __half2*>(&v);
        #pragma unroll
        for (int q = 0; q < 4; q++) {
            float2 f = __half22float2(p[q]);
            acc[2 * q] += f.x; acc[2 * q + 1] += f.y;
        }
    }

    unsigned o[4];
    #pragma unroll
    for (int q = 0; q < 4; q++) {
        __half2 hp = __floats2half2_rn(acc[2 * q], acc[2 * q + 1]);
        o[q] = *reinterpret_cast<unsigned*>(&hp);
    }
    *reinterpret_cast<uint4*>(a_out + (size_t)node * F + c * 8) =
        make_uint4(o[0], o[1], o[2], o[3]);
}

// ---------------------------------------------------------------------------
// fp16 single-pass mma.sync GEMM + bias + ReLU; 3-stage cp.async pipeline +
// ldmatrix.  C = relu( A[M,K] @ Wt^T + b ).  Output fp16 (g_h) or fp32 (out).
//   m16n8k16 atoms. BM=BN=128, BK=32, 256 threads (8 warps, 4x2).
// ---------------------------------------------------------------------------
#define BKK    32
#define SLDA   40
#define STAGES 3
#define TILE_ELEMS (128 * SLDA)
#define GEMM_DSMEM (2 * STAGES * TILE_ELEMS * 2)   // 61440 B dynamic smem

__device__ __forceinline__ void mma_f16(float* c, const unsigned* a, const unsigned* b)
{
    asm volatile(
        "mma.sync.aligned.m16n8k16.row.col.f32.f16.f16.f32 "
        "{%0,%1,%2,%3}, {%4,%5,%6,%7}, {%8,%9}, {%0,%1,%2,%3};"
        : "+f"(c[0]), "+f"(c[1]), "+f"(c[2]), "+f"(c[3])
        : "r"(a[0]), "r"(a[1]), "r"(a[2]), "r"(a[3]),
          "r"(b[0]), "r"(b[1]));
}

__device__ __forceinline__ void cp16(void* smem_dst, const void* gmem_src)
{
    unsigned saddr = (unsigned)__cvta_generic_to_shared(smem_dst);
    asm volatile("cp.async.cg.shared.global [%0], [%1], 16;"
                 :: "r"(saddr), "l"(gmem_src) : "memory");
}

__device__ __forceinline__ void ldsm_x4(unsigned* r, const __half* p)
{
    unsigned a = (unsigned)__cvta_generic_to_shared(p);
    asm volatile("ldmatrix.sync.aligned.m8n8.x4.shared.b16 {%0,%1,%2,%3}, [%4];"
                 : "=r"(r[0]), "=r"(r[1]), "=r"(r[2]), "=r"(r[3]) : "r"(a));
}

__global__ __launch_bounds__(256) void gemm_bias_relu_f16(
    const __half* __restrict__ A,      // [M][K] fp16 aggregates
    const __half* __restrict__ Bw,     // [256][K] transposed fp16 weights
    const float* __restrict__ bias,
    __half* __restrict__ Ch,           // fp16 output (layers 1-2), or null
    float* __restrict__ Cf,            // fp32 output (layer 3), or null
    int M, int K)
{
    extern __shared__ __half dsm[];
    auto At = [&](int st) { return dsm + st * TILE_ELEMS; };
    auto Bt = [&](int st) { return dsm + (STAGES + st) * TILE_ELEMS; };

    int tid  = threadIdx.x;
    int lane = tid & 31;
    int wid  = tid >> 5;
    int warp_m = wid & 3;
    int warp_n = wid >> 2;
    int g = lane >> 2;
    int t = lane & 3;

    int brow = blockIdx.x * 128;
    int bcol = blockIdx.y * 128;

    float acc[2][8][4];
    #pragma unroll
    for (int ma = 0; ma < 2; ma++)
        #pragma unroll
        for (int na = 0; na < 8; na++)
            #pragma unroll
            for (int j = 0; j < 4; j++) acc[ma][na][j] = 0.f;

    // Global->SMEM mapping: row = tid>>1, 32B segment = (tid&1)*16 halves.
    int ld_row = tid >> 1;
    int ld_seg = (tid & 1) * 16;
    int ld_off = ld_row * SLDA + ld_seg;

    int ga_row = brow + ld_row; if (ga_row >= M) ga_row = M - 1;
    const __half* gA  = A  + (size_t)ga_row * K + ld_seg;
    const __half* gBw = Bw + (size_t)(bcol + ld_row) * K + ld_seg;

    int nk = K / BKK;

    // Issue stage loads; always commits a group (empty groups keep the
    // wait_group arithmetic uniform at the pipeline tail).
    auto issue = [&](int st, int i) {
        if (i < nk) {
            int k0 = i * BKK;
            cp16(At(st) + ld_off,     gA + k0);
            cp16(At(st) + ld_off + 8, gA + k0 + 8);
            cp16(Bt(st) + ld_off,     gBw + k0);
            cp16(Bt(st) + ld_off + 8, gBw + k0 + 8);
        }
        asm volatile("cp.async.commit_group;" ::: "memory");
    };

    issue(0, 0);
    issue(1, 1);

    // ldmatrix per-lane address components.
    int a_row8 = (lane & 7) + 8 * ((lane >> 3) & 1);
    int a_koff = 8 * (lane >> 4);
    int b_row8 = (lane & 7) + 8 * (lane >> 4);
    int b_koff = 8 * ((lane >> 3) & 1);

    for (int i = 0; i < nk; i++) {
        int st = i % STAGES;
        asm volatile("cp.async.wait_group %0;" :: "n"(STAGES - 2) : "memory");
        __syncthreads();
        issue((i + 2) % STAGES, i + 2);

        const __half* Ah = At(st);
        const __half* Bh = Bt(st);

        #pragma unroll
        for (int ks = 0; ks < BKK; ks += 16) {
            unsigned a_fr[2][4];
            #pragma unroll
            for (int ma = 0; ma < 2; ma++) {
                int r = warp_m * 32 + ma * 16 + a_row8;
                ldsm_x4(a_fr[ma], Ah + r * SLDA + ks + a_koff);
            }

            #pragma unroll
            for (int np = 0; np < 4; np++) {
                int col = warp_n * 64 + np * 16 + b_row8;
                unsigned bh[4];
                ldsm_x4(bh, Bh + col * SLDA + ks + b_koff);
                #pragma unroll
                for (int half = 0; half < 2; half++) {
                    int na = np * 2 + half;
                    #pragma unroll
                    for (int ma = 0; ma < 2; ma++)
                        mma_f16(acc[ma][na], a_fr[ma], bh + 2 * half);
                }
            }
        }
        __syncthreads();
    }

    // Epilogue: bias + relu; fp16 store (half2) or fp32 store (float2).
    #pragma unroll
    for (int na = 0; na < 8; na++) {
        int col = bcol + warp_n * 64 + na * 8 + t * 2;
        float b0 = bias[col];
        float b1 = bias[col + 1];
        #pragma unroll
        for (int ma = 0; ma < 2; ma++) {
            int row0 = brow + warp_m * 32 + ma * 16 + g;
            int row1 = row0 + 8;
            float x0 = fmaxf(acc[ma][na][0] + b0, 0.f);
            float y0 = fmaxf(acc[ma][na][1] + b1, 0.f);
            float x1 = fmaxf(acc[ma][na][2] + b0, 0.f);
            float y1 = fmaxf(acc[ma][na][3] + b1, 0.f);
            if (Ch) {
                if (row0 < M) {
                    __half2 o = __floats2half2_rn(x0, y0);
                    *reinterpret_cast<__half2*>(Ch + (size_t)row0 * NOUT + col) = o;
                }
                if (row1 < M) {
                    __half2 o = __floats2half2_rn(x1, y1);
                    *reinterpret_cast<__half2*>(Ch + (size_t)row1 * NOUT + col) = o;
                }
            } else {
                if (row0 < M)
                    *reinterpret_cast<float2*>(Cf + (size_t)row0 * NOUT + col) =
                        make_float2(x0, y0);
                if (row1 < M)
                    *reinterpret_cast<float2*>(Cf + (size_t)row1 * NOUT + col) =
                        make_float2(x1, y1);
            }
        }
    }
}

// ---------------------------------------------------------------------------
// Launch orchestration
// ---------------------------------------------------------------------------
static inline void launch_gemm(const __half* a, const __half* wt,
                               const float* b, __half* out_h, float* out_f,
                               int K)
{
    dim3 grid((N_NODES + 127) / 128, NOUT / 128);
    gemm_bias_relu_f16<<<grid, 256, GEMM_DSMEM>>>(a, wt, b, out_h, out_f,
                                                  N_NODES, K);
}

extern "C" void kernel_launch(void* const* d_in, const int* in_sizes, int n_in,
                              void* d_out, int out_size)
{
    const float* x  = (const float*)d_in[0];       // [50000,128]
    const void*  ei = d_in[1];                     // [2,800000] int32 OR int64
    const float* W1 = (const float*)d_in[2];       // [128,256]
    const float* b1 = (const float*)d_in[3];
    const float* W2 = (const float*)d_in[4];       // [256,256]
    const float* b2 = (const float*)d_in[5];
    const float* W3 = (const float*)d_in[6];       // [256,256]
    const float* b3 = (const float*)d_in[7];
    float* out = (float*)d_out;                    // [50000,256]

    static bool attr_done = false;
    if (!attr_done) {
        cudaFuncSetAttribute(gemm_bias_relu_f16,
                             cudaFuncAttributeMaxDynamicSharedMemorySize,
                             GEMM_DSMEM);
        attr_done = true;
    }

    __half *h, *a, *x16, *wt;
    cudaGetSymbolAddress((void**)&h,   g_h);
    cudaGetSymbolAddress((void**)&a,   g_a);
    cudaGetSymbolAddress((void**)&x16, g_x16);
    cudaGetSymbolAddress((void**)&wt,  g_wt);

    // CSR build (+x conversion in hist): hist(1) scan(2) fill(3)
    //   -> 4th launch = layer-1 aggregation (profiled slot)
    hist_kernel<<<(N_EDGES + 255) / 256, 256>>>(ei, x);
    scan_kernel<<<1, 1024>>>();
    fill_kernel<<<(N_EDGES + 255) / 256, 256>>>(ei);

    // Layer 1: aggregate fp16 x16 -> fp16 a (4th launch), weights, GEMM.
    aggregate_f16in<128><<<(N_NODES + 15) / 16, 256>>>(x16, a);
    wsplit_kernel<<<dim3(256, 3), 256>>>(W1, W2, W3);
    launch_gemm(a, wt + 0 * 65536, b1, h, nullptr, 128);

    // Layer 2
    aggregate_f16in<256><<<(N_NODES + 7) / 8, 256>>>(h, a);
    launch_gemm(a, wt + 1 * 65536, b2, h, nullptr, 256);

    // Layer 3 -> fp32 out.
    aggregate_f16in<256><<<(N_NODES + 7) / 8, 256>>>(h, a);
    launch_gemm(a, wt + 2 * 65536, b3, nullptr, out, 256);
}

// round 17
// speedup vs baseline: 1.0195x; 1.0195x over previous
#include <cuda_runtime.h>
#include <cuda_fp16.h>
#include <cstdint>

// ---------------------------------------------------------------------------
// GCN: 3 layers of  h = relu(segment_sum_{(s->d)}(h_prev[s]) @ W + b)
// Aggregate-before-transform (segment_sum is linear).
// Round 17: revert agg to pair-level HADD2 (quad tree regressed: agg is at
//           its L2/latency floor, not issue-bound); fold weight transpose/
//           quantize into hist_kernel (one fewer launch).
// ---------------------------------------------------------------------------

#define N_NODES 50000
#define N_EDGES 800000
#define FMAX    256
#define NOUT    256

// Scratch (static device globals — zero-initialized; no runtime allocation).
__device__ __half  g_h[(size_t)N_NODES * FMAX];     // activations (fp16)
__device__ __half  g_a[(size_t)N_NODES * FMAX];     // aggregates  (fp16)
__device__ __half  g_x16[(size_t)N_NODES * 128];    // x quantized to fp16
__device__ __half  g_wt[3][256 * 256];              // W^T fp16  [N][K]
__device__ int     g_counts[N_NODES];
__device__ int     g_offsets[N_NODES + 1];
__device__ int     g_cursor[N_NODES];
__device__ int     g_perm_src[N_EDGES];

// ---------------------------------------------------------------------------
// Per-block edge-index dtype detection (JAX may have downcast int64->int32).
// ---------------------------------------------------------------------------
__device__ __forceinline__ int block_detect_is64(const void* ei)
{
    long long v = ((const long long*)ei)[threadIdx.x & 255];
    int ok = (v >= 0 && v < N_NODES);
    return __syncthreads_and(ok);
}

// ---------------------------------------------------------------------------
// hist_kernel: in-degree histogram + x fp32->fp16 conversion + weight
// transpose/quantize, all folded into one pass over 800K threads.
// ---------------------------------------------------------------------------
__global__ __launch_bounds__(256) void hist_kernel(const void* __restrict__ ei,
                                                   const float* __restrict__ x,
                                                   const float* __restrict__ W1,
                                                   const float* __restrict__ W2,
                                                   const float* __restrict__ W3)
{
    int is64 = block_detect_is64(ei);
    int e = blockIdx.x * blockDim.x + threadIdx.x;
    if (e >= N_EDGES) return;

    // x conversion: elements e and e + N_EDGES of the float4 view.
    {
        const float4* xf = reinterpret_cast<const float4*>(x);
        uint2* xo = reinterpret_cast<uint2*>(g_x16);
        float4 v0 = xf[e];
        float4 v1 = xf[e + N_EDGES];
        __half2 a0 = __floats2half2_rn(v0.x, v0.y);
        __half2 a1 = __floats2half2_rn(v0.z, v0.w);
        __half2 b0 = __floats2half2_rn(v1.x, v1.y);
        __half2 b1 = __floats2half2_rn(v1.z, v1.w);
        xo[e] = make_uint2(*reinterpret_cast<unsigned*>(&a0),
                           *reinterpret_cast<unsigned*>(&a1));
        xo[e + N_EDGES] = make_uint2(*reinterpret_cast<unsigned*>(&b0),
                                     *reinterpret_cast<unsigned*>(&b1));
    }

    // Weight transpose + fp16 quantize: 32768 + 65536 + 65536 elements.
    // Consecutive e -> consecutive k: coalesced 2B writes into g_wt[l][n*K+k].
    if (e < 32768 + 2 * 65536) {
        int l, n, k, K;
        const float* W;
        if (e < 32768)        { l = 0; K = 128; k = e & 127;  n = e >> 7;  W = W1; }
        else if (e < 98304)   { int t = e - 32768;  l = 1; K = 256; k = t & 255; n = t >> 8; W = W2; }
        else                  { int t = e - 98304;  l = 2; K = 256; k = t & 255; n = t >> 8; W = W3; }
        g_wt[l][n * K + k] = __float2half_rn(W[(size_t)k * NOUT + n]);
    }

    long long d = is64 ? ((const long long*)ei)[N_EDGES + e]
                       : (long long)((const int*)ei)[N_EDGES + e];
    if ((unsigned long long)d < N_NODES) atomicAdd(&g_counts[(int)d], 1);
}

__global__ __launch_bounds__(1024) void scan_kernel()
{
    __shared__ int partial[1024];
    int t = threadIdx.x;
    const int CHUNK = (N_NODES + 1023) / 1024;
    int beg = t * CHUNK;
    int end = beg + CHUNK; if (end > N_NODES) end = N_NODES;
    if (beg > N_NODES) beg = N_NODES;

    int s = 0;
    for (int i = beg; i < end; i++) s += g_counts[i];
    partial[t] = s;
    __syncthreads();
    for (int off = 1; off < 1024; off <<= 1) {
        int v = (t >= off) ? partial[t - off] : 0;
        __syncthreads();
        partial[t] += v;
        __syncthreads();
    }
    int prefix = (t == 0) ? 0 : partial[t - 1];
    for (int i = beg; i < end; i++) {
        g_offsets[i] = prefix;
        g_cursor[i]  = prefix;
        prefix += g_counts[i];
        g_counts[i] = 0;                   // re-zero for next graph replay
    }
    if (t == 1023) g_offsets[N_NODES] = partial[1023];
}

__global__ __launch_bounds__(256) void fill_kernel(const void* __restrict__ ei)
{
    int is64 = block_detect_is64(ei);
    int e = blockIdx.x * blockDim.x + threadIdx.x;
    if (e >= N_EDGES) return;
    long long d, s;
    if (is64) {
        d = ((const long long*)ei)[N_EDGES + e];
        s = ((const long long*)ei)[e];
    } else {
        d = ((const int*)ei)[N_EDGES + e];
        s = ((const int*)ei)[e];
    }
    if ((unsigned long long)d >= N_NODES || (unsigned long long)s >= N_NODES)
        return;
    int pos = atomicAdd(&g_cursor[(int)d], 1);
    g_perm_src[pos] = (int)s;
}

// ---------------------------------------------------------------------------
// CSR aggregation, fp16 input -> fp16 aggregate.
// Edge pairs summed in fp16 (HADD2) before fp32 accumulation (R15-proven).
// CH = F/8 threads per node, uint4 (8-half) gathers, 8-edge unroll.
// ---------------------------------------------------------------------------
template <int F>
__global__ __launch_bounds__(256) void aggregate_f16in(
    const __half* __restrict__ h,
    __half* __restrict__ a_out)
{
    constexpr int CH  = F / 8;            // 16 (F=128) / 32 (F=256)
    constexpr int NPB = 256 / CH;
    int node = blockIdx.x * NPB + threadIdx.x / CH;
    int c    = threadIdx.x % CH;
    if (node >= N_NODES) return;

    int beg = g_offsets[node];
    int end = g_offsets[node + 1];

    float acc[8] = {0.f, 0.f, 0.f, 0.f, 0.f, 0.f, 0.f, 0.f};
    int i = beg;
    for (; i + 8 <= end; i += 8) {
        int s[8];
        #pragma unroll
        for (int j = 0; j < 8; j++) s[j] = g_perm_src[i + j];
        uint4 v[8];
        #pragma unroll
        for (int j = 0; j < 8; j++)
            v[j] = *reinterpret_cast<const uint4*>(h + (size_t)s[j] * F + c * 8);
        // Pairwise fp16 sums (4 HADD2 per pair), then convert+accumulate.
        #pragma unroll
        for (int pr = 0; pr < 4; pr++) {
            const __half2* p0 = reinterpret_cast<const __half2*>(&v[2 * pr]);
            const __half2* p1 = reinterpret_cast<const __half2*>(&v[2 * pr + 1]);
            #pragma unroll
            for (int q = 0; q < 4; q++) {
                __half2 ps = __hadd2(p0[q], p1[q]);
                float2 f = __half22float2(ps);
                acc[2 * q] += f.x; acc[2 * q + 1] += f.y;
            }
        }
    }
    for (; i < end; i++) {
        int s = g_perm_src[i];
        uint4 v = *reinterpret_cast<const uint4*>(h + (size_t)s * F + c * 8);
        const __half2* p = reinterpret_cast<const __half2*>(&v);
        #pragma unroll
        for (int q = 0; q < 4; q++) {
            float2 f = __half22float2(p[q]);
            acc[2 * q] += f.x; acc[2 * q + 1] += f.y;
        }
    }

    unsigned o[4];
    #pragma unroll
    for (int q = 0; q < 4; q++) {
        __half2 hp = __floats2half2_rn(acc[2 * q], acc[2 * q + 1]);
        o[q] = *reinterpret_cast<unsigned*>(&hp);
    }
    *reinterpret_cast<uint4*>(a_out + (size_t)node * F + c * 8) =
        make_uint4(o[0], o[1], o[2], o[3]);
}

// ---------------------------------------------------------------------------
// fp16 single-pass mma.sync GEMM + bias + ReLU; 3-stage cp.async pipeline +
// ldmatrix.  C = relu( A[M,K] @ Wt^T + b ).  Output fp16 (g_h) or fp32 (out).
//   m16n8k16 atoms. BM=BN=128, BK=32, 256 threads (8 warps, 4x2).
// ---------------------------------------------------------------------------
#define BKK    32
#define SLDA   40
#define STAGES 3
#define TILE_ELEMS (128 * SLDA)
#define GEMM_DSMEM (2 * STAGES * TILE_ELEMS * 2)   // 61440 B dynamic smem

__device__ __forceinline__ void mma_f16(float* c, const unsigned* a, const unsigned* b)
{
    asm volatile(
        "mma.sync.aligned.m16n8k16.row.col.f32.f16.f16.f32 "
        "{%0,%1,%2,%3}, {%4,%5,%6,%7}, {%8,%9}, {%0,%1,%2,%3};"
        : "+f"(c[0]), "+f"(c[1]), "+f"(c[2]), "+f"(c[3])
        : "r"(a[0]), "r"(a[1]), "r"(a[2]), "r"(a[3]),
          "r"(b[0]), "r"(b[1]));
}

__device__ __forceinline__ void cp16(void* smem_dst, const void* gmem_src)
{
    unsigned saddr = (unsigned)__cvta_generic_to_shared(smem_dst);
    asm volatile("cp.async.cg.shared.global [%0], [%1], 16;"
                 :: "r"(saddr), "l"(gmem_src) : "memory");
}

__device__ __forceinline__ void ldsm_x4(unsigned* r, const __half* p)
{
    unsigned a = (unsigned)__cvta_generic_to_shared(p);
    asm volatile("ldmatrix.sync.aligned.m8n8.x4.shared.b16 {%0,%1,%2,%3}, [%4];"
                 : "=r"(r[0]), "=r"(r[1]), "=r"(r[2]), "=r"(r[3]) : "r"(a));
}

__global__ __launch_bounds__(256) void gemm_bias_relu_f16(
    const __half* __restrict__ A,      // [M][K] fp16 aggregates
    const __half* __restrict__ Bw,     // [256][K] transposed fp16 weights
    const float* __restrict__ bias,
    __half* __restrict__ Ch,           // fp16 output (layers 1-2), or null
    float* __restrict__ Cf,            // fp32 output (layer 3), or null
    int M, int K)
{
    extern __shared__ __half dsm[];
    auto At = [&](int st) { return dsm + st * TILE_ELEMS; };
    auto Bt = [&](int st) { return dsm + (STAGES + st) * TILE_ELEMS; };

    int tid  = threadIdx.x;
    int lane = tid & 31;
    int wid  = tid >> 5;
    int warp_m = wid & 3;
    int warp_n = wid >> 2;
    int g = lane >> 2;
    int t = lane & 3;

    int brow = blockIdx.x * 128;
    int bcol = blockIdx.y * 128;

    float acc[2][8][4];
    #pragma unroll
    for (int ma = 0; ma < 2; ma++)
        #pragma unroll
        for (int na = 0; na < 8; na++)
            #pragma unroll
            for (int j = 0; j < 4; j++) acc[ma][na][j] = 0.f;

    // Global->SMEM mapping: row = tid>>1, 32B segment = (tid&1)*16 halves.
    int ld_row = tid >> 1;
    int ld_seg = (tid & 1) * 16;
    int ld_off = ld_row * SLDA + ld_seg;

    int ga_row = brow + ld_row; if (ga_row >= M) ga_row = M - 1;
    const __half* gA  = A  + (size_t)ga_row * K + ld_seg;
    const __half* gBw = Bw + (size_t)(bcol + ld_row) * K + ld_seg;

    int nk = K / BKK;

    // Issue stage loads; always commits a group (empty groups keep the
    // wait_group arithmetic uniform at the pipeline tail).
    auto issue = [&](int st, int i) {
        if (i < nk) {
            int k0 = i * BKK;
            cp16(At(st) + ld_off,     gA + k0);
            cp16(At(st) + ld_off + 8, gA + k0 + 8);
            cp16(Bt(st) + ld_off,     gBw + k0);
            cp16(Bt(st) + ld_off + 8, gBw + k0 + 8);
        }
        asm volatile("cp.async.commit_group;" ::: "memory");
    };

    issue(0, 0);
    issue(1, 1);

    // ldmatrix per-lane address components.
    int a_row8 = (lane & 7) + 8 * ((lane >> 3) & 1);
    int a_koff = 8 * (lane >> 4);
    int b_row8 = (lane & 7) + 8 * (lane >> 4);
    int b_koff = 8 * ((lane >> 3) & 1);

    for (int i = 0; i < nk; i++) {
        int st = i % STAGES;
        asm volatile("cp.async.wait_group %0;" :: "n"(STAGES - 2) : "memory");
        __syncthreads();
        issue((i + 2) % STAGES, i + 2);

        const __half* Ah = At(st);
        const __half* Bh = Bt(st);

        #pragma unroll
        for (int ks = 0; ks < BKK; ks += 16) {
            unsigned a_fr[2][4];
            #pragma unroll
            for (int ma = 0; ma < 2; ma++) {
                int r = warp_m * 32 + ma * 16 + a_row8;
                ldsm_x4(a_fr[ma], Ah + r * SLDA + ks + a_koff);
            }

            #pragma unroll
            for (int np = 0; np < 4; np++) {
                int col = warp_n * 64 + np * 16 + b_row8;
                unsigned bh[4];
                ldsm_x4(bh, Bh + col * SLDA + ks + b_koff);
                #pragma unroll
                for (int half = 0; half < 2; half++) {
                    int na = np * 2 + half;
                    #pragma unroll
                    for (int ma = 0; ma < 2; ma++)
                        mma_f16(acc[ma][na], a_fr[ma], bh + 2 * half);
                }
            }
        }
        __syncthreads();
    }

    // Epilogue: bias + relu; fp16 store (half2) or fp32 store (float2).
    #pragma unroll
    for (int na = 0; na < 8; na++) {
        int col = bcol + warp_n * 64 + na * 8 + t * 2;
        float b0 = bias[col];
        float b1 = bias[col + 1];
        #pragma unroll
        for (int ma = 0; ma < 2; ma++) {
            int row0 = brow + warp_m * 32 + ma * 16 + g;
            int row1 = row0 + 8;
            float x0 = fmaxf(acc[ma][na][0] + b0, 0.f);
            float y0 = fmaxf(acc[ma][na][1] + b1, 0.f);
            float x1 = fmaxf(acc[ma][na][2] + b0, 0.f);
            float y1 = fmaxf(acc[ma][na][3] + b1, 0.f);
            if (Ch) {
                if (row0 < M) {
                    __half2 o = __floats2half2_rn(x0, y0);
                    *reinterpret_cast<__half2*>(Ch + (size_t)row0 * NOUT + col) = o;
                }
                if (row1 < M) {
                    __half2 o = __floats2half2_rn(x1, y1);
                    *reinterpret_cast<__half2*>(Ch + (size_t)row1 * NOUT + col) = o;
                }
            } else {
                if (row0 < M)
                    *reinterpret_cast<float2*>(Cf + (size_t)row0 * NOUT + col) =
                        make_float2(x0, y0);
                if (row1 < M)
                    *reinterpret_cast<float2*>(Cf + (size_t)row1 * NOUT + col) =
                        make_float2(x1, y1);
            }
        }
    }
}

// ---------------------------------------------------------------------------
// Launch orchestration
// ---------------------------------------------------------------------------
static inline void launch_gemm(const __half* a, const __half* wt,
                               const float* b, __half* out_h, float* out_f,
                               int K)
{
    dim3 grid((N_NODES + 127) / 128, NOUT / 128);
    gemm_bias_relu_f16<<<grid, 256, GEMM_DSMEM>>>(a, wt, b, out_h, out_f,
                                                  N_NODES, K);
}

extern "C" void kernel_launch(void* const* d_in, const int* in_sizes, int n_in,
                              void* d_out, int out_size)
{
    const float* x  = (const float*)d_in[0];       // [50000,128]
    const void*  ei = d_in[1];                     // [2,800000] int32 OR int64
    const float* W1 = (const float*)d_in[2];       // [128,256]
    const float* b1 = (const float*)d_in[3];
    const float* W2 = (const float*)d_in[4];       // [256,256]
    const float* b2 = (const float*)d_in[5];
    const float* W3 = (const float*)d_in[6];       // [256,256]
    const float* b3 = (const float*)d_in[7];
    float* out = (float*)d_out;                    // [50000,256]

    static bool attr_done = false;
    if (!attr_done) {
        cudaFuncSetAttribute(gemm_bias_relu_f16,
                             cudaFuncAttributeMaxDynamicSharedMemorySize,
                             GEMM_DSMEM);
        attr_done = true;
    }

    __half *h, *a, *x16, *wt;
    cudaGetSymbolAddress((void**)&h,   g_h);
    cudaGetSymbolAddress((void**)&a,   g_a);
    cudaGetSymbolAddress((void**)&x16, g_x16);
    cudaGetSymbolAddress((void**)&wt,  g_wt);

    // CSR build (+x conversion +weight prep in hist): hist(1) scan(2) fill(3)
    //   -> 4th launch = layer-1 aggregation (profiled slot)
    hist_kernel<<<(N_EDGES + 255) / 256, 256>>>(ei, x, W1, W2, W3);
    scan_kernel<<<1, 1024>>>();
    fill_kernel<<<(N_EDGES + 255) / 256, 256>>>(ei);

    // Layer 1: aggregate fp16 x16 -> fp16 a (4th launch), then GEMM.
    aggregate_f16in<128><<<(N_NODES + 15) / 16, 256>>>(x16, a);
    launch_gemm(a, wt + 0 * 65536, b1, h, nullptr, 128);

    // Layer 2
    aggregate_f16in<256><<<(N_NODES + 7) / 8, 256>>>(h, a);
    launch_gemm(a, wt + 1 * 65536, b2, h, nullptr, 256);

    // Layer 3 -> fp32 out.
    aggregate_f16in<256><<<(N_NODES + 7) / 8, 256>>>(h, a);
    launch_gemm(a, wt + 2 * 65536, b3, nullptr, out, 256);
}